// round 14
// baseline (speedup 1.0000x reference)
#include <cuda_runtime.h>
#include <cuda_fp16.h>
#include <cstdint>

#define GNUM 8
#define DIN 1024
#define DOUT 1024
#define RNK 16
#define SCALEF 2.0f

#define BM 128
#define BN 128
#define KC 64                 // K elements per chunk
#define NCHUNK 17             // 16 real K-chunks + 1 LoRA chunk (K=16, 1 kstep)
#define MAX_N 8192
#define MAX_TILES ((MAX_N / BM) + GNUM)   // 72
#define CHUNK_U4 1024         // one 128x64 fp16 matrix image (16KB), in uint4

#define MAT_B 16384
#define STAGE_B 32768         // A image + B image
#define SMEM_MAIN (2 * STAGE_B)   // 64KB -> 2 CTAs/SM

// megaprep block ranges
#define PRE_A   (MAX_TILES * 4)              // 288  (LoRA-A, 4 blocks/tile)
#define PRE_B   (PRE_A + MAX_TILES * 16)     // 1440 (A images)
#define PRE_LB  (PRE_B + GNUM * 8 * 16)      // 2464 (B images)
#define PRE_TOT (PRE_LB + GNUM * 8)          // 2528 (LoRA-B images)

// ---------------- device scratch (no allocations allowed) ----------------
__device__ int g_tile_row0[MAX_TILES];
__device__ int g_tile_rows[MAX_TILES];
__device__ int g_tile_grp[MAX_TILES];
__device__ uint4 gA[MAX_TILES * NCHUNK * CHUNK_U4];   // fp16 A images [m][k]
__device__ uint4 gB[GNUM * 8 * NCHUNK * CHUNK_U4];    // fp16 B images [n][k]

// ---------------- PTX helpers (baseline ISA only; no 'a'-features) ----------------
__device__ __forceinline__ uint32_t smem_u32(const void* p) {
    uint32_t a;
    asm("{ .reg .u64 t; cvta.to.shared.u64 t, %1; cvt.u32.u64 %0, t; }" : "=r"(a) : "l"(p));
    return a;
}
#define MBARRIER_INIT(a, c) \
    asm volatile("mbarrier.init.shared.b64 [%0], %1;" :: "r"((uint32_t)(a)), "r"((uint32_t)(c)) : "memory")
#define MBARRIER_EXPECT_TX(a, tx) \
    asm volatile("mbarrier.arrive.expect_tx.shared.b64 _, [%0], %1;" \
                 :: "r"((uint32_t)(a)), "r"((uint32_t)(tx)) : "memory")
#define MBARRIER_WAIT_PARITY(a, ph) do { \
    uint32_t _m = (uint32_t)(a); uint32_t _p = (uint32_t)(ph); uint32_t _d; \
    asm volatile("{\n\t.reg .pred p;\n\t" \
        "mbarrier.try_wait.parity.acquire.cta.shared::cta.b64 p, [%1], %2;\n\t" \
        "selp.b32 %0, 1, 0, p;\n\t}" : "=r"(_d) : "r"(_m), "r"(_p) : "memory"); \
    if (!_d) { \
        asm volatile("{\n\t.reg .pred P1;\n\t" \
            "WL_%=:\n\t" \
            "mbarrier.try_wait.parity.acquire.cta.shared::cta.b64 P1, [%0], %1, 0x989680;\n\t" \
            "@P1 bra.uni WD_%=;\n\tbra.uni WL_%=;\n\tWD_%=:\n\t}" \
            :: "r"(_m), "r"(_p) : "memory"); \
    } } while (0)
#define CP_BULK(dst, src, bytes, mb) \
    asm volatile("cp.async.bulk.shared::cluster.global.mbarrier::complete_tx::bytes " \
                 "[%0], [%1], %2, [%3];" \
                 :: "r"((uint32_t)(dst)), "l"(src), "r"((uint32_t)(bytes)), \
                    "r"((uint32_t)(mb)) : "memory")

__device__ __forceinline__ void ldm_x4(uint32_t* r, uint32_t addr) {
    asm volatile("ldmatrix.sync.aligned.m8n8.x4.shared.b16 {%0,%1,%2,%3}, [%4];"
                 : "=r"(r[0]), "=r"(r[1]), "=r"(r[2]), "=r"(r[3]) : "r"(addr));
}
__device__ __forceinline__ void mma_f16(float* d, const uint32_t* a, uint32_t b0, uint32_t b1) {
    asm volatile("mma.sync.aligned.m16n8k16.row.col.f32.f16.f16.f32 "
                 "{%0,%1,%2,%3}, {%4,%5,%6,%7}, {%8,%9}, {%0,%1,%2,%3};"
                 : "+f"(d[0]), "+f"(d[1]), "+f"(d[2]), "+f"(d[3])
                 : "r"(a[0]), "r"(a[1]), "r"(a[2]), "r"(a[3]), "r"(b0), "r"(b1));
}

// ---------------- fp16 pack + swizzled image write ----------------
__device__ __forceinline__ uint4 pack8h(const float* v) {
    uint32_t h[4];
#pragma unroll
    for (int p = 0; p < 4; p++) {
        __half2 hp = __floats2half2_rn(v[2 * p], v[2 * p + 1]);
        h[p] = *reinterpret_cast<uint32_t*>(&hp);
    }
    return make_uint4(h[0], h[1], h[2], h[3]);
}
__device__ __forceinline__ void write_img(uint4* base, int row, int kq, const float* v) {
    uint32_t s = (uint32_t)row * 8u + (((uint32_t)kq >> 3) ^ ((uint32_t)row & 7u));
    base[s] = pack8h(v);
}

__device__ __forceinline__ int get_group(const int* p, int i, int is64) {
    return is64 ? p[2 * i] : p[i];
}

// cooperative group-boundary search: st[0..8] = starts, st[9] = is64 flag
__device__ __forceinline__ void find_starts(const int* gr, int N, int* st) {
    int t = threadIdx.x;
    if (t == 0) {
        int wl = gr[N - 1], wp = gr[N - 2];
        st[GNUM + 1] = (wl == 0 && wp != 0) ? 1 : 0;   // int64 dtype hedge
    }
    __syncthreads();
    int is64 = st[GNUM + 1];
    if (t <= GNUM) {
        int lo = 0, hi = N;
        while (lo < hi) {
            int mid = (lo + hi) >> 1;
            if (get_group(gr, mid, is64) < t) lo = mid + 1;
            else hi = mid;
        }
        st[t] = lo;
    }
    __syncthreads();
}

__device__ __forceinline__ bool tile_info(const int* st, int tile,
                                          int& row0, int& rows, int& grp) {
    int nt = 0;
#pragma unroll
    for (int g = 0; g < GNUM; g++) {
        int s = st[g], e = st[g + 1];
        int cnt = (e - s + BM - 1) / BM;
        if (tile < nt + cnt) {
            row0 = s + (tile - nt) * BM;
            rows = min(BM, e - row0);
            grp = g;
            return true;
        }
        nt += cnt;
    }
    return false;
}

// ---------------- kernel 1: fused prep (lora_a->image, A images, B images, LoRA-B) ---
__global__ __launch_bounds__(256) void megaprep(const float* __restrict__ x,
                                                const float* __restrict__ Wb,
                                                const float* __restrict__ WA,
                                                const float* __restrict__ WBl,
                                                const int* __restrict__ gr, int N) {
    __shared__ __align__(16) float S[KC][129];
    __shared__ int s_start[GNUM + 2];
    int b = blockIdx.x;
    int t = threadIdx.x;

    if (b < PRE_A) {
        // ---- LoRA-A: SCALE*(x@W_A[g]) -> fp16 image chunk 16; 4 blocks/tile, 32 rows each
        find_starts(gr, N, s_start);
        if (b == 0 && t < MAX_TILES) {          // publish tile table for main_gemm
            int r0, rw, gp;
            if (tile_info(s_start, t, r0, rw, gp)) {
                g_tile_row0[t] = r0; g_tile_rows[t] = rw; g_tile_grp[t] = gp;
            } else {
                g_tile_rows[t] = 0;
            }
        }
        int tile = b >> 2, quarter = b & 3;
        int row0, rows, grp;
        if (!tile_info(s_start, tile, row0, rows, grp)) return;

        float* Xs  = &S[0][0];                  // [32][36] = 1152 floats
        float* WsT = Xs + 32 * 36;              // [16][36] = 576 floats (transposed W_A)
        int rloc = t >> 3;                      // 0..31 local row
        int rq   = (t & 7) * 2;                 // 2 of 16 r-outputs
        int mrow = quarter * 32 + rloc;         // row within tile
        int grow = quarter * 32 + (t >> 3);     // row for the Xs fill
        const float* wg = WA + (size_t)grp * DIN * RNK;

        float acc0 = 0.f, acc1 = 0.f;
        for (int kb = 0; kb < DIN; kb += 32) {
            __syncthreads();
            {   // WsT fill: [16][36] transposed, 2 elems/thread, coalesced-ish gmem reads
                int kk = t >> 3, r8 = t & 7;
                float w0 = wg[(size_t)(kb + kk) * RNK + r8];
                float w1 = wg[(size_t)(kb + kk) * RNK + r8 + 8];
                WsT[r8 * 36 + kk]       = w0;
                WsT[(r8 + 8) * 36 + kk] = w1;
            }
            {   // Xs fill: [32][36] pitch-36 (float4 aligned), coalesced 16B loads
                int c0 = (t & 7) * 4;
                float4 v;
                if (grow < rows)
                    v = *(const float4*)(x + (size_t)(row0 + grow) * DIN + kb + c0);
                else
                    v = make_float4(0.f, 0.f, 0.f, 0.f);
                *(float4*)&Xs[(t >> 3) * 36 + c0] = v;
            }
            __syncthreads();
#pragma unroll
            for (int kk = 0; kk < 32; kk += 4) {
                float4 xq = *(const float4*)&Xs[rloc * 36 + kk];
                float4 w0 = *(const float4*)&WsT[rq * 36 + kk];
                float4 w1 = *(const float4*)&WsT[(rq + 1) * 36 + kk];
                acc0 += xq.x * w0.x + xq.y * w0.y + xq.z * w0.z + xq.w * w0.w;
                acc1 += xq.x * w1.x + xq.y * w1.y + xq.z * w1.z + xq.w * w1.w;
            }
        }
        // store 2 fp16 outputs at swizzled position (4B aligned within 16B unit)
        __half2 h = __floats2half2_rn(SCALEF * acc0, SCALEF * acc1);
        uint32_t unit = (uint32_t)rq >> 3;     // 0 or 1
        uint32_t s = (uint32_t)mrow * 8u + (unit ^ ((uint32_t)mrow & 7u));
        char* dst = (char*)(gA + ((size_t)(tile * NCHUNK + 16)) * CHUNK_U4)
                    + s * 16 + (rq & 7) * 2;
        *(uint32_t*)dst = *reinterpret_cast<uint32_t*>(&h);
    } else if (b < PRE_B) {
        // ---- A tile image (fp16, swizzled): tile, chunk ci
        find_starts(gr, N, s_start);
        int idx = b - PRE_A;
        int tile = idx >> 4, ci = idx & 15;
        int row0, rows, grp;
        if (!tile_info(s_start, tile, row0, rows, grp)) return;

        int kq = (t & 7) * 8;
        uint4* base = gA + ((size_t)(tile * NCHUNK + ci)) * CHUNK_U4;
#pragma unroll
        for (int it = 0; it < 4; it++) {
            int r = (t >> 3) + it * 32;
            float v[8];
            if (r < rows) {
                const float* p = x + (size_t)(row0 + r) * DIN + ci * KC + kq;
                float4 a = *(const float4*)p;
                float4 c = *(const float4*)(p + 4);
                v[0] = a.x; v[1] = a.y; v[2] = a.z; v[3] = a.w;
                v[4] = c.x; v[5] = c.y; v[6] = c.z; v[7] = c.w;
            } else {
#pragma unroll
                for (int j = 0; j < 8; j++) v[j] = 0.f;
            }
            write_img(base, r, kq, v);
        }
    } else if (b < PRE_LB) {
        // ---- B image: transpose W_base[g] chunk ci, cols [ncb*128, +128) -> [n][k]
        int idx = b - PRE_B;
        int bx = idx >> 4, ci = idx & 15;      // bx = g*8 + ncb
        int g = bx >> 3, ncb = bx & 7;
        const float* W = Wb + (size_t)g * DIN * DOUT + (size_t)ci * KC * DOUT + ncb * BN;
        int c4 = (t & 31) * 4;
        int kr0 = t >> 5;
#pragma unroll
        for (int i = 0; i < 8; i++) {
            int kr = kr0 + i * 8;
            float4 v = *(const float4*)(W + (size_t)kr * DOUT + c4);
            S[kr][c4 + 0] = v.x; S[kr][c4 + 1] = v.y;
            S[kr][c4 + 2] = v.z; S[kr][c4 + 3] = v.w;
        }
        __syncthreads();
        int kq = (t & 7) * 8;
        uint4* base = gB + ((size_t)(bx * NCHUNK + ci)) * CHUNK_U4;
#pragma unroll
        for (int it = 0; it < 4; it++) {
            int r = (t >> 3) + it * 32;        // n-row
            float v[8];
#pragma unroll
            for (int j = 0; j < 8; j++) v[j] = S[kq + j][r];
            write_img(base, r, kq, v);
        }
    } else {
        // ---- LoRA-B image (chunk 16): W_B[g][k][n] -> [n][k], k<16
        int idx = b - PRE_LB;                  // 0..63 : g*8+ncb
        int g = idx >> 3, ncb = idx & 7;
        int r  = t >> 1;
        int kq = (t & 1) * 8;
        uint4* base = gB + ((size_t)(idx * NCHUNK + 16)) * CHUNK_U4;
        float v[8];
#pragma unroll
        for (int j = 0; j < 8; j++)
            v[j] = WBl[((size_t)g * RNK + kq + j) * DOUT + ncb * BN + r];
        write_img(base, r, kq, v);
    }
}

// ---------------- kernel 2: fp16 1-pass mma.sync GEMM, 2-stage bulk pipeline -------
__global__ __launch_bounds__(256, 2) void main_gemm(float* __restrict__ out) {
    int tile = blockIdx.x;
    int rows = g_tile_rows[tile];
    if (rows == 0) return;
    int row0 = g_tile_row0[tile];
    int grp  = g_tile_grp[tile];
    int ncb  = blockIdx.y;
    int col0 = ncb * BN;

    extern __shared__ char smem[];
    __shared__ __align__(16) uint64_t mbar[2];
    uint32_t sbase = smem_u32(smem);
    int t = threadIdx.x;
    int lane = t & 31, warp = t >> 5;
    int wm = warp & 3;        // m-quadrant
    int wn = warp >> 2;       // n-half

    uint32_t mbs[2] = {smem_u32(&mbar[0]), smem_u32(&mbar[1])};
    if (t == 0) {
        MBARRIER_INIT(mbs[0], 1);
        MBARRIER_INIT(mbs[1], 1);
    }
    __syncthreads();

    const uint4* srcA = gA + (size_t)tile * NCHUNK * CHUNK_U4;
    const uint4* srcB = gB + (size_t)(grp * 8 + ncb) * NCHUNK * CHUNK_U4;

    if (t == 0) {
        MBARRIER_EXPECT_TX(mbs[0], STAGE_B);
        CP_BULK(sbase,         (const void*)srcA, MAT_B, mbs[0]);
        CP_BULK(sbase + MAT_B, (const void*)srcB, MAT_B, mbs[0]);
        MBARRIER_EXPECT_TX(mbs[1], STAGE_B);
        CP_BULK(sbase + STAGE_B,         (const void*)(srcA + CHUNK_U4), MAT_B, mbs[1]);
        CP_BULK(sbase + STAGE_B + MAT_B, (const void*)(srcB + CHUNK_U4), MAT_B, mbs[1]);
    }

    // per-thread fragment address components (swizzled layout)
    int lr = lane & 15;
    int hf = lane >> 4;       // +8 k-elements half
    uint32_t rowA[2], swA[2], rowB[4], swB[4];
#pragma unroll
    for (int i = 0; i < 2; i++) {
        int rr = wm * 32 + i * 16 + lr;
        rowA[i] = (uint32_t)rr * 128u;
        swA[i]  = (uint32_t)(rr & 7);
    }
#pragma unroll
    for (int jp = 0; jp < 4; jp++) {
        int rr = wn * 64 + jp * 16 + lr;
        rowB[jp] = (uint32_t)rr * 128u;
        swB[jp]  = (uint32_t)(rr & 7);
    }

    float acc[2][8][4];
#pragma unroll
    for (int i = 0; i < 2; i++)
#pragma unroll
        for (int j = 0; j < 8; j++)
#pragma unroll
            for (int q = 0; q < 4; q++) acc[i][j][q] = 0.f;

    for (int ci = 0; ci < NCHUNK; ci++) {
        int s = ci & 1;
        MBARRIER_WAIT_PARITY(mbs[s], (ci >> 1) & 1);

        uint32_t stg = sbase + (uint32_t)s * STAGE_B;
        int ksteps = (ci == NCHUNK - 1) ? 1 : 4;   // LoRA chunk: K=16 = 1 kstep
        for (int ks = 0; ks < ksteps; ks++) {
            uint32_t u = (uint32_t)(ks * 2 + hf);
            uint32_t aF[2][4];
#pragma unroll
            for (int i = 0; i < 2; i++)
                ldm_x4(aF[i], stg + rowA[i] + ((u ^ swA[i]) << 4));
            uint32_t bF[4][4];
#pragma unroll
            for (int jp = 0; jp < 4; jp++)
                ldm_x4(bF[jp], stg + MAT_B + rowB[jp] + ((u ^ swB[jp]) << 4));
#pragma unroll
            for (int i = 0; i < 2; i++)
#pragma unroll
                for (int jp = 0; jp < 4; jp++)
#pragma unroll
                    for (int w2 = 0; w2 < 2; w2++) {
                        int j = jp * 2 + w2;
                        mma_f16(acc[i][j], aF[i], bF[jp][w2], bF[jp][w2 + 2]);
                    }
        }
        __syncthreads();
        if (t == 0 && ci + 2 < NCHUNK) {
            MBARRIER_EXPECT_TX(mbs[s], STAGE_B);
            CP_BULK(stg,         (const void*)(srcA + (size_t)(ci + 2) * CHUNK_U4), MAT_B, mbs[s]);
            CP_BULK(stg + MAT_B, (const void*)(srcB + (size_t)(ci + 2) * CHUNK_U4), MAT_B, mbs[s]);
        }
    }

    // ---- epilogue: direct stores (each element written exactly once) ----
    int lr4 = lane >> 2;
    int lc2 = 2 * (lane & 3);
#pragma unroll
    for (int i = 0; i < 2; i++) {
        int mloc0 = wm * 32 + i * 16 + lr4;
#pragma unroll
        for (int j = 0; j < 8; j++) {
            int c = col0 + wn * 64 + j * 8 + lc2;
            if (mloc0 < rows) {
                float2 v = make_float2(acc[i][j][0], acc[i][j][1]);
                *(float2*)(out + (size_t)(row0 + mloc0) * DOUT + c) = v;
            }
            if (mloc0 + 8 < rows) {
                float2 v = make_float2(acc[i][j][2], acc[i][j][3]);
                *(float2*)(out + (size_t)(row0 + mloc0 + 8) * DOUT + c) = v;
            }
        }
    }
}

// ---------------- launch ----------------
extern "C" void kernel_launch(void* const* d_in, const int* in_sizes, int n_in,
                              void* d_out, int out_size) {
    const float* x   = (const float*)d_in[0];
    const int*   xg  = (const int*)d_in[1];   // x_groups (int32, int64-hedged)
    const float* Wb  = (const float*)d_in[2]; // [G, DIN, DOUT]
    const float* WA  = (const float*)d_in[3]; // [G, DIN, R]
    const float* WBl = (const float*)d_in[4]; // [G, R, DOUT]
    float* out = (float*)d_out;

    int N = in_sizes[0] / DIN;

    cudaFuncSetAttribute(main_gemm, cudaFuncAttributeMaxDynamicSharedMemorySize, SMEM_MAIN);

    megaprep<<<PRE_TOT, 256>>>(x, Wb, WA, WBl, xg, N);
    dim3 gm(MAX_TILES, DOUT / BN);
    main_gemm<<<gm, 256, SMEM_MAIN>>>(out);
}

// round 17
// speedup vs baseline: 1.5743x; 1.5743x over previous
#include <cuda_runtime.h>
#include <cuda_fp16.h>
#include <cstdint>

#define GNUM 8
#define DIN 1024
#define DOUT 1024
#define RNK 16
#define SCALEF 2.0f

#define BM 128
#define BN 128
#define KC 64                 // K elements per chunk
#define NCHUNK 17             // 16 real K-chunks + 1 LoRA chunk (K=16, 1 kstep)
#define MAX_N 8192
#define MAX_TILES ((MAX_N / BM) + GNUM)   // 72
#define CHUNK_U4 1024         // one 128x64 fp16 matrix image (16KB), in uint4

#define MAT_B 16384
#define STAGE_B 32768         // A image + B image
#define SMEM_MAIN (2 * STAGE_B)   // 64KB -> 2 CTAs/SM

// megaprep block ranges
#define PRE_A   (MAX_TILES * 2)              // 144  (LoRA-A, 2 blocks/tile)
#define PRE_B   (PRE_A + MAX_TILES * 16)     // 1296 (A images)
#define PRE_LB  (PRE_B + GNUM * 8 * 16)      // 2320 (B images)
#define PRE_TOT (PRE_LB + GNUM * 8)          // 2384 (LoRA-B images)

// ---------------- device scratch (no allocations allowed) ----------------
__device__ int g_tile_row0[MAX_TILES];
__device__ int g_tile_rows[MAX_TILES];
__device__ int g_tile_grp[MAX_TILES];
__device__ uint4 gA[MAX_TILES * NCHUNK * CHUNK_U4];   // fp16 A images [m][k]
__device__ uint4 gB[GNUM * 8 * NCHUNK * CHUNK_U4];    // fp16 B images [n][k]

// ---------------- PTX helpers (baseline ISA only; no 'a'-features) ----------------
__device__ __forceinline__ uint32_t smem_u32(const void* p) {
    uint32_t a;
    asm("{ .reg .u64 t; cvta.to.shared.u64 t, %1; cvt.u32.u64 %0, t; }" : "=r"(a) : "l"(p));
    return a;
}
#define MBARRIER_INIT(a, c) \
    asm volatile("mbarrier.init.shared.b64 [%0], %1;" :: "r"((uint32_t)(a)), "r"((uint32_t)(c)) : "memory")
#define MBARRIER_EXPECT_TX(a, tx) \
    asm volatile("mbarrier.arrive.expect_tx.shared.b64 _, [%0], %1;" \
                 :: "r"((uint32_t)(a)), "r"((uint32_t)(tx)) : "memory")
#define MBARRIER_WAIT_PARITY(a, ph) do { \
    uint32_t _m = (uint32_t)(a); uint32_t _p = (uint32_t)(ph); uint32_t _d; \
    asm volatile("{\n\t.reg .pred p;\n\t" \
        "mbarrier.try_wait.parity.acquire.cta.shared::cta.b64 p, [%1], %2;\n\t" \
        "selp.b32 %0, 1, 0, p;\n\t}" : "=r"(_d) : "r"(_m), "r"(_p) : "memory"); \
    if (!_d) { \
        asm volatile("{\n\t.reg .pred P1;\n\t" \
            "WL_%=:\n\t" \
            "mbarrier.try_wait.parity.acquire.cta.shared::cta.b64 P1, [%0], %1, 0x989680;\n\t" \
            "@P1 bra.uni WD_%=;\n\tbra.uni WL_%=;\n\tWD_%=:\n\t}" \
            :: "r"(_m), "r"(_p) : "memory"); \
    } } while (0)
#define CP_BULK(dst, src, bytes, mb) \
    asm volatile("cp.async.bulk.shared::cluster.global.mbarrier::complete_tx::bytes " \
                 "[%0], [%1], %2, [%3];" \
                 :: "r"((uint32_t)(dst)), "l"(src), "r"((uint32_t)(bytes)), \
                    "r"((uint32_t)(mb)) : "memory")

__device__ __forceinline__ void ldm_x4(uint32_t* r, uint32_t addr) {
    asm volatile("ldmatrix.sync.aligned.m8n8.x4.shared.b16 {%0,%1,%2,%3}, [%4];"
                 : "=r"(r[0]), "=r"(r[1]), "=r"(r[2]), "=r"(r[3]) : "r"(addr));
}
__device__ __forceinline__ void mma_f16(float* d, const uint32_t* a, uint32_t b0, uint32_t b1) {
    asm volatile("mma.sync.aligned.m16n8k16.row.col.f32.f16.f16.f32 "
                 "{%0,%1,%2,%3}, {%4,%5,%6,%7}, {%8,%9}, {%0,%1,%2,%3};"
                 : "+f"(d[0]), "+f"(d[1]), "+f"(d[2]), "+f"(d[3])
                 : "r"(a[0]), "r"(a[1]), "r"(a[2]), "r"(a[3]), "r"(b0), "r"(b1));
}

// ---------------- fp16 pack + swizzled image write ----------------
__device__ __forceinline__ uint4 pack8h(const float* v) {
    uint32_t h[4];
#pragma unroll
    for (int p = 0; p < 4; p++) {
        __half2 hp = __floats2half2_rn(v[2 * p], v[2 * p + 1]);
        h[p] = *reinterpret_cast<uint32_t*>(&hp);
    }
    return make_uint4(h[0], h[1], h[2], h[3]);
}
__device__ __forceinline__ void write_img(uint4* base, int row, int kq, const float* v) {
    uint32_t s = (uint32_t)row * 8u + (((uint32_t)kq >> 3) ^ ((uint32_t)row & 7u));
    base[s] = pack8h(v);
}

__device__ __forceinline__ int get_group(const int* p, int i, int is64) {
    return is64 ? p[2 * i] : p[i];
}

// cooperative group-boundary search: st[0..8] = starts, st[9] = is64 flag
__device__ __forceinline__ void find_starts(const int* gr, int N, int* st) {
    int t = threadIdx.x;
    if (t == 0) {
        int wl = gr[N - 1], wp = gr[N - 2];
        st[GNUM + 1] = (wl == 0 && wp != 0) ? 1 : 0;   // int64 dtype hedge
    }
    __syncthreads();
    int is64 = st[GNUM + 1];
    if (t <= GNUM) {
        int lo = 0, hi = N;
        while (lo < hi) {
            int mid = (lo + hi) >> 1;
            if (get_group(gr, mid, is64) < t) lo = mid + 1;
            else hi = mid;
        }
        st[t] = lo;
    }
    __syncthreads();
}

__device__ __forceinline__ bool tile_info(const int* st, int tile,
                                          int& row0, int& rows, int& grp) {
    int nt = 0;
#pragma unroll
    for (int g = 0; g < GNUM; g++) {
        int s = st[g], e = st[g + 1];
        int cnt = (e - s + BM - 1) / BM;
        if (tile < nt + cnt) {
            row0 = s + (tile - nt) * BM;
            rows = min(BM, e - row0);
            grp = g;
            return true;
        }
        nt += cnt;
    }
    return false;
}

// ---------------- kernel 1: fused prep (lora_a->image, A images, B images, LoRA-B) ---
__global__ __launch_bounds__(256) void megaprep(const float* __restrict__ x,
                                                const float* __restrict__ Wb,
                                                const float* __restrict__ WA,
                                                const float* __restrict__ WBl,
                                                const int* __restrict__ gr, int N) {
    __shared__ __align__(16) float S[KC][129];
    __shared__ int s_start[GNUM + 2];
    int b = blockIdx.x;
    int t = threadIdx.x;

    if (b < PRE_A) {
        // ---- LoRA-A: SCALE*(x@W_A[g]) -> fp16 image chunk 16; 2 blocks/tile, 64 rows each
        find_starts(gr, N, s_start);
        if (b == 0 && t < MAX_TILES) {          // publish tile table for main_gemm
            int r0, rw, gp;
            if (tile_info(s_start, t, r0, rw, gp)) {
                g_tile_row0[t] = r0; g_tile_rows[t] = rw; g_tile_grp[t] = gp;
            } else {
                g_tile_rows[t] = 0;
            }
        }
        int tile = b >> 1, half = b & 1;
        int row0, rows, grp;
        if (!tile_info(s_start, tile, row0, rows, grp)) return;

        float* Xs = &S[0][0];                   // [64][33] padded = 2112 floats
        float* Ws = Xs + 64 * 33;               // [32][16] = 512 floats
        int rloc = t >> 2;                      // 0..63 local row
        int rq   = (t & 3) * 4;                 // 4 of 16 r-outputs
        int mrow = half * 64 + rloc;            // row within tile
        const float* wg = WA + (size_t)grp * DIN * RNK;

        float acc[4] = {0.f, 0.f, 0.f, 0.f};
        for (int kb = 0; kb < DIN; kb += 32) {
            __syncthreads();
            if (t < 128) {                      // Ws chunk [32][16]
                int kk = t >> 2, c = (t & 3) * 4;
                *(float4*)&Ws[kk * 16 + c] =
                    *(const float4*)(wg + (size_t)(kb + kk) * RNK + c);
            }
            {                                   // Xs chunk [64][32], coalesced
                int r = t >> 2;
                int c0 = (t & 3) * 8;
                int grow = half * 64 + r;
                if (grow < rows) {
                    const float* p = x + (size_t)(row0 + grow) * DIN + kb + c0;
                    float4 a = *(const float4*)p;
                    float4 c = *(const float4*)(p + 4);
                    float* d = &Xs[r * 33 + c0];
                    d[0] = a.x; d[1] = a.y; d[2] = a.z; d[3] = a.w;
                    d[4] = c.x; d[5] = c.y; d[6] = c.z; d[7] = c.w;
                } else {
                    float* d = &Xs[r * 33 + c0];
#pragma unroll
                    for (int j = 0; j < 8; j++) d[j] = 0.f;
                }
            }
            __syncthreads();
#pragma unroll
            for (int kk = 0; kk < 32; kk++) {
                float xv = Xs[rloc * 33 + kk];
#pragma unroll
                for (int u = 0; u < 4; u++) acc[u] += xv * Ws[kk * 16 + rq + u];
            }
        }
        // store 4 fp16 outputs at swizzled position (8B aligned)
        __half2 h0 = __floats2half2_rn(SCALEF * acc[0], SCALEF * acc[1]);
        __half2 h1 = __floats2half2_rn(SCALEF * acc[2], SCALEF * acc[3]);
        uint32_t unit = (uint32_t)rq >> 3;     // 0 or 1
        uint32_t s = (uint32_t)mrow * 8u + (unit ^ ((uint32_t)mrow & 7u));
        char* dst = (char*)(gA + ((size_t)(tile * NCHUNK + 16)) * CHUNK_U4)
                    + s * 16 + (rq & 7) * 2;
        uint2 st2;
        st2.x = *reinterpret_cast<uint32_t*>(&h0);
        st2.y = *reinterpret_cast<uint32_t*>(&h1);
        *(uint2*)dst = st2;
    } else if (b < PRE_B) {
        // ---- A tile image (fp16, swizzled): tile, chunk ci
        find_starts(gr, N, s_start);
        int idx = b - PRE_A;
        int tile = idx >> 4, ci = idx & 15;
        int row0, rows, grp;
        if (!tile_info(s_start, tile, row0, rows, grp)) return;

        int kq = (t & 7) * 8;
        uint4* base = gA + ((size_t)(tile * NCHUNK + ci)) * CHUNK_U4;
#pragma unroll
        for (int it = 0; it < 4; it++) {
            int r = (t >> 3) + it * 32;
            float v[8];
            if (r < rows) {
                const float* p = x + (size_t)(row0 + r) * DIN + ci * KC + kq;
                float4 a = *(const float4*)p;
                float4 c = *(const float4*)(p + 4);
                v[0] = a.x; v[1] = a.y; v[2] = a.z; v[3] = a.w;
                v[4] = c.x; v[5] = c.y; v[6] = c.z; v[7] = c.w;
            } else {
#pragma unroll
                for (int j = 0; j < 8; j++) v[j] = 0.f;
            }
            write_img(base, r, kq, v);
        }
    } else if (b < PRE_LB) {
        // ---- B image: transpose W_base[g] chunk ci, cols [ncb*128, +128) -> [n][k]
        int idx = b - PRE_B;
        int bx = idx >> 4, ci = idx & 15;      // bx = g*8 + ncb
        int g = bx >> 3, ncb = bx & 7;
        const float* W = Wb + (size_t)g * DIN * DOUT + (size_t)ci * KC * DOUT + ncb * BN;
        int c4 = (t & 31) * 4;
        int kr0 = t >> 5;
#pragma unroll
        for (int i = 0; i < 8; i++) {
            int kr = kr0 + i * 8;
            float4 v = *(const float4*)(W + (size_t)kr * DOUT + c4);
            S[kr][c4 + 0] = v.x; S[kr][c4 + 1] = v.y;
            S[kr][c4 + 2] = v.z; S[kr][c4 + 3] = v.w;
        }
        __syncthreads();
        int kq = (t & 7) * 8;
        uint4* base = gB + ((size_t)(bx * NCHUNK + ci)) * CHUNK_U4;
#pragma unroll
        for (int it = 0; it < 4; it++) {
            int r = (t >> 3) + it * 32;        // n-row
            float v[8];
#pragma unroll
            for (int j = 0; j < 8; j++) v[j] = S[kq + j][r];
            write_img(base, r, kq, v);
        }
    } else {
        // ---- LoRA-B image (chunk 16): W_B[g][k][n] -> [n][k], k<16
        int idx = b - PRE_LB;                  // 0..63 : g*8+ncb
        int g = idx >> 3, ncb = idx & 7;
        int r  = t >> 1;
        int kq = (t & 1) * 8;
        uint4* base = gB + ((size_t)(idx * NCHUNK + 16)) * CHUNK_U4;
        float v[8];
#pragma unroll
        for (int j = 0; j < 8; j++)
            v[j] = WBl[((size_t)g * RNK + kq + j) * DOUT + ncb * BN + r];
        write_img(base, r, kq, v);
    }
}

// ---------------- kernel 2: fp16 1-pass mma.sync GEMM, 2-stage bulk pipeline -------
__global__ __launch_bounds__(256, 2) void main_gemm(float* __restrict__ out) {
    int tile = blockIdx.x;
    int rows = g_tile_rows[tile];
    if (rows == 0) return;
    int row0 = g_tile_row0[tile];
    int grp  = g_tile_grp[tile];
    int ncb  = blockIdx.y;
    int col0 = ncb * BN;

    extern __shared__ char smem[];
    __shared__ __align__(16) uint64_t mbar[2];
    uint32_t sbase = smem_u32(smem);
    int t = threadIdx.x;
    int lane = t & 31, warp = t >> 5;
    int wm = warp & 3;        // m-quadrant
    int wn = warp >> 2;       // n-half

    uint32_t mbs[2] = {smem_u32(&mbar[0]), smem_u32(&mbar[1])};
    if (t == 0) {
        MBARRIER_INIT(mbs[0], 1);
        MBARRIER_INIT(mbs[1], 1);
    }
    __syncthreads();

    const uint4* srcA = gA + (size_t)tile * NCHUNK * CHUNK_U4;
    const uint4* srcB = gB + (size_t)(grp * 8 + ncb) * NCHUNK * CHUNK_U4;

    if (t == 0) {
        MBARRIER_EXPECT_TX(mbs[0], STAGE_B);
        CP_BULK(sbase,         (const void*)srcA, MAT_B, mbs[0]);
        CP_BULK(sbase + MAT_B, (const void*)srcB, MAT_B, mbs[0]);
        MBARRIER_EXPECT_TX(mbs[1], STAGE_B);
        CP_BULK(sbase + STAGE_B,         (const void*)(srcA + CHUNK_U4), MAT_B, mbs[1]);
        CP_BULK(sbase + STAGE_B + MAT_B, (const void*)(srcB + CHUNK_U4), MAT_B, mbs[1]);
    }

    // per-thread fragment address components (swizzled layout)
    int lr = lane & 15;
    int hf = lane >> 4;       // +8 k-elements half
    uint32_t rowA[2], swA[2], rowB[4], swB[4];
#pragma unroll
    for (int i = 0; i < 2; i++) {
        int rr = wm * 32 + i * 16 + lr;
        rowA[i] = (uint32_t)rr * 128u;
        swA[i]  = (uint32_t)(rr & 7);
    }
#pragma unroll
    for (int jp = 0; jp < 4; jp++) {
        int rr = wn * 64 + jp * 16 + lr;
        rowB[jp] = (uint32_t)rr * 128u;
        swB[jp]  = (uint32_t)(rr & 7);
    }

    float acc[2][8][4];
#pragma unroll
    for (int i = 0; i < 2; i++)
#pragma unroll
        for (int j = 0; j < 8; j++)
#pragma unroll
            for (int q = 0; q < 4; q++) acc[i][j][q] = 0.f;

    for (int ci = 0; ci < NCHUNK; ci++) {
        int s = ci & 1;
        MBARRIER_WAIT_PARITY(mbs[s], (ci >> 1) & 1);

        uint32_t stg = sbase + (uint32_t)s * STAGE_B;
        int ksteps = (ci == NCHUNK - 1) ? 1 : 4;   // LoRA chunk: K=16 = 1 kstep
        for (int ks = 0; ks < ksteps; ks++) {
            uint32_t u = (uint32_t)(ks * 2 + hf);
            uint32_t aF[2][4];
#pragma unroll
            for (int i = 0; i < 2; i++)
                ldm_x4(aF[i], stg + rowA[i] + ((u ^ swA[i]) << 4));
            uint32_t bF[4][4];
#pragma unroll
            for (int jp = 0; jp < 4; jp++)
                ldm_x4(bF[jp], stg + MAT_B + rowB[jp] + ((u ^ swB[jp]) << 4));
#pragma unroll
            for (int i = 0; i < 2; i++)
#pragma unroll
                for (int jp = 0; jp < 4; jp++)
#pragma unroll
                    for (int w2 = 0; w2 < 2; w2++) {
                        int j = jp * 2 + w2;
                        mma_f16(acc[i][j], aF[i], bF[jp][w2], bF[jp][w2 + 2]);
                    }
        }
        __syncthreads();
        if (t == 0 && ci + 2 < NCHUNK) {
            MBARRIER_EXPECT_TX(mbs[s], STAGE_B);
            CP_BULK(stg,         (const void*)(srcA + (size_t)(ci + 2) * CHUNK_U4), MAT_B, mbs[s]);
            CP_BULK(stg + MAT_B, (const void*)(srcB + (size_t)(ci + 2) * CHUNK_U4), MAT_B, mbs[s]);
        }
    }

    // ---- epilogue: direct stores (each element written exactly once) ----
    int lr4 = lane >> 2;
    int lc2 = 2 * (lane & 3);
#pragma unroll
    for (int i = 0; i < 2; i++) {
        int mloc0 = wm * 32 + i * 16 + lr4;
#pragma unroll
        for (int j = 0; j < 8; j++) {
            int c = col0 + wn * 64 + j * 8 + lc2;
            if (mloc0 < rows) {
                float2 v = make_float2(acc[i][j][0], acc[i][j][1]);
                *(float2*)(out + (size_t)(row0 + mloc0) * DOUT + c) = v;
            }
            if (mloc0 + 8 < rows) {
                float2 v = make_float2(acc[i][j][2], acc[i][j][3]);
                *(float2*)(out + (size_t)(row0 + mloc0 + 8) * DOUT + c) = v;
            }
        }
    }
}

// ---------------- launch ----------------
extern "C" void kernel_launch(void* const* d_in, const int* in_sizes, int n_in,
                              void* d_out, int out_size) {
    const float* x   = (const float*)d_in[0];
    const int*   xg  = (const int*)d_in[1];   // x_groups (int32, int64-hedged)
    const float* Wb  = (const float*)d_in[2]; // [G, DIN, DOUT]
    const float* WA  = (const float*)d_in[3]; // [G, DIN, R]
    const float* WBl = (const float*)d_in[4]; // [G, R, DOUT]
    float* out = (float*)d_out;

    int N = in_sizes[0] / DIN;

    cudaFuncSetAttribute(main_gemm, cudaFuncAttributeMaxDynamicSharedMemorySize, SMEM_MAIN);

    megaprep<<<PRE_TOT, 256>>>(x, Wb, WA, WBl, xg, N);
    dim3 gm(MAX_TILES, DOUT / BN);
    main_gemm<<<gm, 256, SMEM_MAIN>>>(out);
}